// round 5
// baseline (speedup 1.0000x reference)
#include <cuda_runtime.h>
#include <cuda_bf16.h>
#include <stdint.h>
#include <math.h>

// Problem constants: B=4, C=64, H=W=64, P=4096.
#define BATCH 4
#define CCH   64
#define PPIX  4096
#define LOG2E 1.4426950408889634f

// ---------------------------------------------------------------------------
// Device scratch (no allocation allowed). Split bf16: x = hi + lo (~16 bits).
// ---------------------------------------------------------------------------
__device__ __nv_bfloat16 g_Qh[BATCH * PPIX * CCH];  // Y boxsum  [b][p][c]
__device__ __nv_bfloat16 g_Ql[BATCH * PPIX * CCH];
__device__ __nv_bfloat16 g_Kh[BATCH * PPIX * CCH];  // K-hat     [b][p][c]
__device__ __nv_bfloat16 g_Kl[BATCH * PPIX * CCH];
__device__ float         g_m [BATCH * PPIX];        // |Y_q| (softmax max bound)

// ---------------------------------------------------------------------------
// helpers (baseline PTX only: mma.sync / ldmatrix / cp.async)
// ---------------------------------------------------------------------------
__device__ __forceinline__ uint32_t smem_u32(const void* p) {
    uint32_t a;
    asm("{ .reg .u64 t; cvta.to.shared.u64 t, %1; cvt.u32.u64 %0, t; }" : "=r"(a) : "l"(p));
    return a;
}
__device__ __forceinline__ uint32_t lds32(uint32_t a) {
    uint32_t v; asm volatile("ld.shared.b32 %0, [%1];" : "=r"(v) : "r"(a)); return v;
}
__device__ __forceinline__ void ldsm4t(uint32_t* r, uint32_t addr) {
    asm volatile("ldmatrix.sync.aligned.m8n8.x4.trans.shared.b16 {%0,%1,%2,%3}, [%4];"
        : "=r"(r[0]), "=r"(r[1]), "=r"(r[2]), "=r"(r[3]) : "r"(addr));
}
__device__ __forceinline__ void mma16816(float* d, const uint32_t* a, uint32_t b0, uint32_t b1) {
    asm volatile(
        "mma.sync.aligned.m16n8k16.row.col.f32.bf16.bf16.f32 "
        "{%0,%1,%2,%3}, {%4,%5,%6,%7}, {%8,%9}, {%0,%1,%2,%3};"
        : "+f"(d[0]), "+f"(d[1]), "+f"(d[2]), "+f"(d[3])
        : "r"(a[0]), "r"(a[1]), "r"(a[2]), "r"(a[3]), "r"(b0), "r"(b1));
}
__device__ __forceinline__ float ex2(float x) {
    float r; asm("ex2.approx.ftz.f32 %0, %1;" : "=f"(r) : "f"(x)); return r;
}
__device__ __forceinline__ void split_bf16(float x, __nv_bfloat16& h, __nv_bfloat16& l) {
    h = __float2bfloat16_rn(x);
    l = __float2bfloat16_rn(x - __bfloat162float(h));
}
__device__ __forceinline__ void split2(float p0, float p1, uint32_t& hp, uint32_t& lp) {
    __nv_bfloat16 h0, l0, h1, l1;
    split_bf16(p0, h0, l0);
    split_bf16(p1, h1, l1);
    hp = (uint32_t)__bfloat16_as_ushort(h0) | ((uint32_t)__bfloat16_as_ushort(h1) << 16);
    lp = (uint32_t)__bfloat16_as_ushort(l0) | ((uint32_t)__bfloat16_as_ushort(l1) << 16);
}

// K tile smem geometry: [128 k][64 c] bf16, row pitch 144B (128B data + 16B pad)
#define KPITCH    144
#define TILE_H    18432            // 128 * 144
#define BUF_BYTES 36864            // hi + lo
#define SMEM_TOTAL 73728           // two buffers

__device__ __forceinline__ void load_tile(uint32_t dbuf,
                                          const __nv_bfloat16* gKh,
                                          const __nv_bfloat16* gKl,
                                          int k0, int t) {
    #pragma unroll
    for (int c = 0; c < 4; ++c) {
        int idx = t + 256 * c;                 // 0..1023
        int row = idx >> 3, ch = idx & 7;
        uint32_t d = dbuf + row * KPITCH + ch * 16;
        const void* sh = gKh + (size_t)(k0 + row) * CCH + ch * 8;
        const void* sl = gKl + (size_t)(k0 + row) * CCH + ch * 8;
        asm volatile("cp.async.cg.shared.global [%0], [%1], 16;" :: "r"(d), "l"(sh));
        asm volatile("cp.async.cg.shared.global [%0], [%1], 16;" :: "r"(d + TILE_H), "l"(sl));
    }
}

// ---------------------------------------------------------------------------
// prep v2 (unchanged from R4): one CTA per (h row, batch).
// ---------------------------------------------------------------------------
#define VPITCH 67
__global__ void __launch_bounds__(256) prep_kernel(const float* __restrict__ f) {
    const int b = blockIdx.y;
    const int h = blockIdx.x;
    const int t = threadIdx.x;

    __shared__ float vs[CCH * VPITCH];
    __shared__ float fs[CCH * VPITCH];
    __shared__ float rf[4][64], ry[4][64];
    __shared__ float sinv[64];

    const float* fb = f + (size_t)b * CCH * PPIX + h * 64;

    #pragma unroll
    for (int i = t; i < CCH * 64; i += 256) {
        int c = i >> 6, w = i & 63;
        const float* base = fb + (size_t)c * PPIX + w;
        float mid = base[0];
        float top = (h > 0)  ? base[-64] : 0.f;
        float bot = (h < 63) ? base[64]  : 0.f;
        vs[c * VPITCH + w + 1] = top + mid + bot;
        fs[c * VPITCH + w + 1] = mid;
    }
    if (t < CCH) { vs[t * VPITCH] = 0.f; vs[t * VPITCH + 65] = 0.f; }
    __syncthreads();

    {
        const int w = t & 63, s = t >> 6;
        float fsq = 0.f, ysq = 0.f;
        #pragma unroll
        for (int cc = 0; cc < 16; ++cc) {
            int c = s * 16 + cc;
            float fv = fs[c * VPITCH + w + 1];
            float yv = vs[c * VPITCH + w] + vs[c * VPITCH + w + 1] + vs[c * VPITCH + w + 2];
            fsq = fmaf(fv, fv, fsq);
            ysq = fmaf(yv, yv, ysq);
        }
        rf[s][w] = fsq;
        ry[s][w] = ysq;
    }
    __syncthreads();
    if (t < 64) {
        float F = rf[0][t] + rf[1][t] + rf[2][t] + rf[3][t];
        float Y = ry[0][t] + ry[1][t] + ry[2][t] + ry[3][t];
        sinv[t] = 1.f / (sqrtf(F) + 1e-8f);
        g_m[b * PPIX + h * 64 + t] = sqrtf(Y);
    }
    __syncthreads();

    const int c = t & 63, s = t >> 6;
    #pragma unroll
    for (int it = 0; it < 16; ++it) {
        const int w = s * 16 + it;
        const float yv = vs[c * VPITCH + w] + vs[c * VPITCH + w + 1] + vs[c * VPITCH + w + 2];
        const float kv = fs[c * VPITCH + w + 1] * sinv[w];
        const size_t rowbase = ((size_t)(b * PPIX + h * 64 + w)) * CCH + c;
        __nv_bfloat16 hh, ll;
        split_bf16(yv, hh, ll);
        g_Qh[rowbase] = hh; g_Ql[rowbase] = ll;
        split_bf16(kv, hh, ll);
        g_Kh[rowbase] = hh; g_Kl[rowbase] = ll;
    }
}

// ---------------------------------------------------------------------------
// attn: same structure as R4, but MMA issue order restructured so accumulator
// reuse distance is 8 MMA issues (covers HMMA RAW latency at 2 warps/SMSP).
// ---------------------------------------------------------------------------
__global__ void __launch_bounds__(256, 1) attn_kernel(float* __restrict__ out) {
    extern __shared__ char smem[];
    const uint32_t sb = smem_u32(smem);

    const int b    = blockIdx.y;
    const int q0   = blockIdx.x * 128;
    const int t    = threadIdx.x;
    const int lane = t & 31;
    const int wid  = t >> 5;
    const int qi   = wid >> 1, kj = wid & 1;
    const int qo   = qi * 32,  ko = kj * 64;
    const int g    = lane >> 2, tq = lane & 3;

    // ---- persistent Q A-frags (hi/lo) + per-row max bounds ----
    uint32_t qa[2][2][4][4];
    #pragma unroll
    for (int hl = 0; hl < 2; ++hl) {
        const __nv_bfloat16* Qsrc = hl ? g_Ql : g_Qh;
        #pragma unroll
        for (int mi = 0; mi < 2; ++mi) {
            const __nv_bfloat16* r0 = Qsrc + (size_t)(b * PPIX + q0 + qo + 16 * mi + g) * CCH;
            const __nv_bfloat16* r8 = r0 + 8 * CCH;
            #pragma unroll
            for (int s = 0; s < 4; ++s) {
                int c0 = 16 * s + 2 * tq;
                qa[hl][mi][s][0] = *(const uint32_t*)(r0 + c0);
                qa[hl][mi][s][1] = *(const uint32_t*)(r8 + c0);
                qa[hl][mi][s][2] = *(const uint32_t*)(r0 + c0 + 8);
                qa[hl][mi][s][3] = *(const uint32_t*)(r8 + c0 + 8);
            }
        }
    }
    float mk[2][2];
    #pragma unroll
    for (int mi = 0; mi < 2; ++mi)
        #pragma unroll
        for (int h = 0; h < 2; ++h)
            mk[mi][h] = g_m[b * PPIX + q0 + qo + 16 * mi + 8 * h + g] * LOG2E;

    float oacc[2][8][4];
    #pragma unroll
    for (int mi = 0; mi < 2; ++mi)
        #pragma unroll
        for (int n = 0; n < 8; ++n)
            #pragma unroll
            for (int r = 0; r < 4; ++r) oacc[mi][n][r] = 0.f;
    float lsum[2][2] = {{0.f, 0.f}, {0.f, 0.f}};

    const __nv_bfloat16* gKh = g_Kh + (size_t)b * PPIX * CCH;
    const __nv_bfloat16* gKl = g_Kl + (size_t)b * PPIX * CCH;

    // prefetch tile 0
    load_tile(sb, gKh, gKl, 0, t);
    asm volatile("cp.async.commit_group;" ::: "memory");

    const uint32_t laneoff = (uint32_t)(((lane & 7) + 8 * ((lane >> 3) & 1)) * KPITCH
                                        + (lane >> 4) * 16);

    for (int kt = 0; kt < 32; ++kt) {
        __syncthreads();                                  // frees buf[(kt+1)&1]
        if (kt + 1 < 32)
            load_tile(sb + ((kt + 1) & 1) * BUF_BYTES, gKh, gKl, (kt + 1) * 128, t);
        asm volatile("cp.async.commit_group;" ::: "memory");
        asm volatile("cp.async.wait_group 1;" ::: "memory");
        __syncthreads();                                  // buf[kt&1] visible

        const uint32_t aH = sb + (uint32_t)(kt & 1) * BUF_BYTES;
        const uint32_t aL = aH + TILE_H;

        // ---- S = Q.K^T over this warp's 64-key slice ----
        float sacc[2][8][4];
        #pragma unroll
        for (int mi = 0; mi < 2; ++mi)
            #pragma unroll
            for (int j = 0; j < 8; ++j)
                #pragma unroll
                for (int r = 0; r < 4; ++r) sacc[mi][j][r] = 0.f;

        #pragma unroll
        for (int s = 0; s < 4; ++s) {
            #pragma unroll
            for (int jg = 0; jg < 2; ++jg) {
                // stage B-frags for 4 consecutive j (hi and lo)
                uint32_t bh[4][2], bl[4][2];
                #pragma unroll
                for (int j4 = 0; j4 < 4; ++j4) {
                    const int j = jg * 4 + j4;
                    const uint32_t o = (uint32_t)((ko + 8 * j + g) * KPITCH + 4 * tq + 32 * s);
                    bh[j4][0] = lds32(aH + o);
                    bh[j4][1] = lds32(aH + o + 16);
                    bl[j4][0] = lds32(aL + o);
                    bl[j4][1] = lds32(aL + o + 16);
                }
                // Qh*Kh — 8 independent accumulators
                #pragma unroll
                for (int j4 = 0; j4 < 4; ++j4) {
                    const int j = jg * 4 + j4;
                    mma16816(sacc[0][j], qa[0][0][s], bh[j4][0], bh[j4][1]);
                    mma16816(sacc[1][j], qa[0][1][s], bh[j4][0], bh[j4][1]);
                }
                // Ql*Kh
                #pragma unroll
                for (int j4 = 0; j4 < 4; ++j4) {
                    const int j = jg * 4 + j4;
                    mma16816(sacc[0][j], qa[1][0][s], bh[j4][0], bh[j4][1]);
                    mma16816(sacc[1][j], qa[1][1][s], bh[j4][0], bh[j4][1]);
                }
                // Qh*Kl
                #pragma unroll
                for (int j4 = 0; j4 < 4; ++j4) {
                    const int j = jg * 4 + j4;
                    mma16816(sacc[0][j], qa[0][0][s], bl[j4][0], bl[j4][1]);
                    mma16816(sacc[1][j], qa[0][1][s], bl[j4][0], bl[j4][1]);
                }
            }
        }

        // ---- softmax (static max) + split-pack P into A-frags ----
        uint32_t pah[2][4][4], pal[2][4][4];
        #pragma unroll
        for (int mi = 0; mi < 2; ++mi)
            #pragma unroll
            for (int j = 0; j < 8; ++j) {
                float p0 = ex2(fmaf(sacc[mi][j][0], LOG2E, -mk[mi][0]));
                float p1 = ex2(fmaf(sacc[mi][j][1], LOG2E, -mk[mi][0]));
                float p2 = ex2(fmaf(sacc[mi][j][2], LOG2E, -mk[mi][1]));
                float p3 = ex2(fmaf(sacc[mi][j][3], LOG2E, -mk[mi][1]));
                lsum[mi][0] += p0 + p1;
                lsum[mi][1] += p2 + p3;
                uint32_t hp01, lp01, hp23, lp23;
                split2(p0, p1, hp01, lp01);
                split2(p2, p3, hp23, lp23);
                const int s2 = j >> 1, r = (j & 1) * 2;
                pah[mi][s2][r]     = hp01;
                pah[mi][s2][r + 1] = hp23;
                pal[mi][s2][r]     = lp01;
                pal[mi][s2][r + 1] = lp23;
            }

        // ---- O += P.K over this warp's 64-key slice (ldmatrix.trans V) ----
        #pragma unroll
        for (int s2 = 0; s2 < 4; ++s2) {
            const uint32_t base = (uint32_t)((ko + 16 * s2) * KPITCH) + laneoff;
            #pragma unroll
            for (int jpg = 0; jpg < 2; ++jpg) {
                uint32_t bh0[4], bh1[4], bl0[4], bl1[4];
                ldsm4t(bh0, aH + base + (jpg * 2 + 0) * 32);
                ldsm4t(bh1, aH + base + (jpg * 2 + 1) * 32);
                ldsm4t(bl0, aL + base + (jpg * 2 + 0) * 32);
                ldsm4t(bl1, aL + base + (jpg * 2 + 1) * 32);
                const int jpA = jpg * 2, jpB = jpg * 2 + 1;
                // Ph*Vh — 8 independent accumulators per pass
                mma16816(oacc[0][2 * jpA],     pah[0][s2], bh0[0], bh0[1]);
                mma16816(oacc[0][2 * jpA + 1], pah[0][s2], bh0[2], bh0[3]);
                mma16816(oacc[1][2 * jpA],     pah[1][s2], bh0[0], bh0[1]);
                mma16816(oacc[1][2 * jpA + 1], pah[1][s2], bh0[2], bh0[3]);
                mma16816(oacc[0][2 * jpB],     pah[0][s2], bh1[0], bh1[1]);
                mma16816(oacc[0][2 * jpB + 1], pah[0][s2], bh1[2], bh1[3]);
                mma16816(oacc[1][2 * jpB],     pah[1][s2], bh1[0], bh1[1]);
                mma16816(oacc[1][2 * jpB + 1], pah[1][s2], bh1[2], bh1[3]);
                // Pl*Vh
                mma16816(oacc[0][2 * jpA],     pal[0][s2], bh0[0], bh0[1]);
                mma16816(oacc[0][2 * jpA + 1], pal[0][s2], bh0[2], bh0[3]);
                mma16816(oacc[1][2 * jpA],     pal[1][s2], bh0[0], bh0[1]);
                mma16816(oacc[1][2 * jpA + 1], pal[1][s2], bh0[2], bh0[3]);
                mma16816(oacc[0][2 * jpB],     pal[0][s2], bh1[0], bh1[1]);
                mma16816(oacc[0][2 * jpB + 1], pal[0][s2], bh1[2], bh1[3]);
                mma16816(oacc[1][2 * jpB],     pal[1][s2], bh1[0], bh1[1]);
                mma16816(oacc[1][2 * jpB + 1], pal[1][s2], bh1[2], bh1[3]);
                // Ph*Vl
                mma16816(oacc[0][2 * jpA],     pah[0][s2], bl0[0], bl0[1]);
                mma16816(oacc[0][2 * jpA + 1], pah[0][s2], bl0[2], bl0[3]);
                mma16816(oacc[1][2 * jpA],     pah[1][s2], bl0[0], bl0[1]);
                mma16816(oacc[1][2 * jpA + 1], pah[1][s2], bl0[2], bl0[3]);
                mma16816(oacc[0][2 * jpB],     pah[0][s2], bl1[0], bl1[1]);
                mma16816(oacc[0][2 * jpB + 1], pah[0][s2], bl1[2], bl1[3]);
                mma16816(oacc[1][2 * jpB],     pah[1][s2], bl1[0], bl1[1]);
                mma16816(oacc[1][2 * jpB + 1], pah[1][s2], bl1[2], bl1[3]);
            }
        }
    }

    // ---- epilogue: reduce lsum over quad, combine 2 k-warps, normalize ----
    #pragma unroll
    for (int mi = 0; mi < 2; ++mi)
        #pragma unroll
        for (int h = 0; h < 2; ++h) {
            lsum[mi][h] += __shfl_xor_sync(0xffffffffu, lsum[mi][h], 1);
            lsum[mi][h] += __shfl_xor_sync(0xffffffffu, lsum[mi][h], 2);
        }

    float* redO = (float*)smem;                    // [4 qi][32 lanes][68]  (buf0)
    float* redL = (float*)(smem + 34816);          // [128] row lsums       (buf0 tail)
    float* stg  = (float*)(smem + 36864);          // [64 c][132 q]         (buf1)

    if (kj == 1) {
        float* dst = redO + qi * 2176 + lane * 68;
        #pragma unroll
        for (int mi = 0; mi < 2; ++mi)
            #pragma unroll
            for (int n = 0; n < 8; ++n)
                #pragma unroll
                for (int r = 0; r < 4; ++r)
                    dst[(mi * 8 + n) * 4 + r] = oacc[mi][n][r];
        if (tq == 0) {
            #pragma unroll
            for (int mi = 0; mi < 2; ++mi)
                #pragma unroll
                for (int h = 0; h < 2; ++h)
                    redL[qi * 32 + 16 * mi + 8 * h + g] = lsum[mi][h];
        }
    }
    __syncthreads();

    if (kj == 0) {
        const float* src = redO + qi * 2176 + lane * 68;
        float inv[2][2];
        #pragma unroll
        for (int mi = 0; mi < 2; ++mi)
            #pragma unroll
            for (int h = 0; h < 2; ++h)
                inv[mi][h] = 1.f / (lsum[mi][h] + redL[qi * 32 + 16 * mi + 8 * h + g]);
        #pragma unroll
        for (int mi = 0; mi < 2; ++mi)
            #pragma unroll
            for (int n = 0; n < 8; ++n)
                #pragma unroll
                for (int r = 0; r < 4; ++r) {
                    float v = (oacc[mi][n][r] + src[(mi * 8 + n) * 4 + r]) * inv[mi][r >> 1];
                    int q = qo + 16 * mi + g + ((r & 2) ? 8 : 0);
                    int c = 8 * n + 2 * tq + (r & 1);
                    stg[c * 132 + q] = v;
                }
    }
    __syncthreads();

    float* ob = out + (size_t)b * CCH * PPIX;
    #pragma unroll
    for (int it = 0; it < 8; ++it) {
        int i = t + 256 * it;
        int row = i >> 5, f4 = i & 31;
        float4 v = *(const float4*)(stg + row * 132 + f4 * 4);
        *(float4*)(ob + row * PPIX + q0 + 4 * f4) = v;
    }
}

// ---------------------------------------------------------------------------
extern "C" void kernel_launch(void* const* d_in, const int* in_sizes, int n_in,
                              void* d_out, int out_size) {
    const float* f = (const float*)d_in[0];   // foreground [4,64,64,64] fp32
    float* out = (float*)d_out;               // [4,64,64,64] fp32

    prep_kernel<<<dim3(64, 4), 256>>>(f);

    cudaFuncSetAttribute(attn_kernel, cudaFuncAttributeMaxDynamicSharedMemorySize, SMEM_TOTAL);
    attn_kernel<<<dim3(32, 4), 256, SMEM_TOTAL>>>(out);
}